// round 8
// baseline (speedup 1.0000x reference)
#include <cuda_runtime.h>
#include <cuda_fp16.h>
#include <cuda_bf16.h>
#include <cstdint>
#include <math.h>

// ---------------- problem constants ----------------
#define NS    6400          // SAMPLE*SAMPLE patches per image
#define CCH   49            // PATCH*PATCH channels
#define IMGW  512
#define GW    169           // (512-7)/3 + 1 patch-grid size
#define EPSF  2.2204460492503131e-16f
#define LAMB  0.05f
#define KST   168           // row stride in bf16 (160 active K + 8 pad; 336B, ldmatrix conflict-free)

// ---------------- device scratch ----------------
__device__ int   g_base_t[NS];
__device__ int   g_base_r[NS];
__device__ float g_ymean[CCH];
__device__ __nv_bfloat16 g_xr[(size_t)NS * KST];  // target rows [hi49|hi49|lo49|0...]
__device__ __nv_bfloat16 g_yr[(size_t)NS * KST];  // refer  rows [hi49|lo49|hi49|0...]
__device__ __half g_dh[(size_t)NS * NS];          // 81.92 MB distance matrix (fp16)
__device__ unsigned long long g_amin[NS];
__device__ int   g_cnt[NS];
__device__ float g_rowloss[NS];

// ---------------- warp-mma helpers ----------------
__device__ __forceinline__ uint32_t smem_to_u32(const void* p) {
    uint32_t a;
    asm("{ .reg .u64 t; cvta.to.shared.u64 t, %1; cvt.u32.u64 %0, t; }" : "=r"(a) : "l"(p));
    return a;
}
__device__ __forceinline__ void ldsm_x4(uint32_t& r0, uint32_t& r1, uint32_t& r2, uint32_t& r3,
                                        uint32_t addr) {
    asm volatile("ldmatrix.sync.aligned.m8n8.x4.shared.b16 {%0,%1,%2,%3}, [%4];"
                 : "=r"(r0), "=r"(r1), "=r"(r2), "=r"(r3) : "r"(addr));
}
__device__ __forceinline__ void mma16816(float* c, const uint32_t* a, const uint32_t* b) {
    asm volatile("mma.sync.aligned.m16n8k16.row.col.f32.bf16.bf16.f32 "
                 "{%0,%1,%2,%3}, {%4,%5,%6,%7}, {%8,%9}, {%0,%1,%2,%3};"
                 : "+f"(c[0]), "+f"(c[1]), "+f"(c[2]), "+f"(c[3])
                 : "r"(a[0]), "r"(a[1]), "r"(a[2]), "r"(a[3]), "r"(b[0]), "r"(b[1]));
}

// ---------------- 1) grid-sample nearest indices (+ init amin/cnt) ----------------
__global__ void k_idx(const float* __restrict__ tfield, const float* __restrict__ rfield) {
    int i = blockIdx.x * blockDim.x + threadIdx.x;
    if (i < NS) { g_amin[i] = ~0ull; g_cnt[i] = 0; }
    if (i >= 2 * NS) return;
    const float* f = (i < NS) ? tfield : rfield;
    int p = (i < NS) ? i : (i - NS);
    float gx = __fadd_rn(__fmul_rn(f[2 * p + 0], 2.0f), -1.0f);
    float gy = __fadd_rn(__fmul_rn(f[2 * p + 1], 2.0f), -1.0f);
    float fx = __fmul_rn(__fadd_rn(__fmul_rn(__fadd_rn(gx, 1.0f), (float)GW), -1.0f), 0.5f);
    float fy = __fmul_rn(__fadd_rn(__fmul_rn(__fadd_rn(gy, 1.0f), (float)GW), -1.0f), 0.5f);
    int ix = (int)rintf(fx); ix = ix < 0 ? 0 : (ix > GW - 1 ? GW - 1 : ix);
    int iy = (int)rintf(fy); iy = iy < 0 ? 0 : (iy > GW - 1 ? GW - 1 : iy);
    int base = (iy * 3) * IMGW + ix * 3;
    if (i < NS) g_base_t[p] = base; else g_base_r[p] = base;
}

// ---------------- 2) refer patch channel mean ----------------
__global__ void k_mean(const float* __restrict__ rimg) {
    int c = blockIdx.x;
    int off = (c / 7) * IMGW + (c % 7);
    int t = threadIdx.x;
    float s = 0.0f;
    for (int p = t; p < NS; p += 256) s += rimg[g_base_r[p] + off];
    __shared__ float sm[256];
    sm[t] = s; __syncthreads();
    for (int st = 128; st; st >>= 1) { if (t < st) sm[t] += sm[t + st]; __syncthreads(); }
    if (t == 0) g_ymean[c] = sm[0] * (1.0f / (float)NS);
}

// ---------------- 3) features -> bf16 hi/lo split rows ----------------
// X row: [hi(49) | hi(49) | lo(49) | 0] ; Y row: [hi(49) | lo(49) | hi(49) | 0]
// X.Y = hi.hi + hi.lo + lo.hi  (drops only lo.lo ~2^-18)
__global__ void k_feat(const float* __restrict__ timg, const float* __restrict__ rimg) {
    int p = blockIdx.x * 256 + threadIdx.x;           // gridDim.x = 25
    bool is_t = (blockIdx.y == 0);
    const float* img = is_t ? timg : rimg;
    int base = is_t ? g_base_t[p] : g_base_r[p];
    __nv_bfloat16* out = (is_t ? g_xr : g_yr) + (size_t)p * KST;
    float v[CCH];
    float sq = 0.0f;
#pragma unroll
    for (int c = 0; c < CCH; c++) {
        v[c] = img[base + (c / 7) * IMGW + (c % 7)] - g_ymean[c];
        sq += v[c] * v[c];
    }
    float inv = 1.0f / (sqrtf(sq) + EPSF);
#pragma unroll
    for (int c = 0; c < CCH; c++) {
        float val = v[c] * inv;
        __nv_bfloat16 hi = __float2bfloat16(val);
        __nv_bfloat16 lo = __float2bfloat16(val - __bfloat162float(hi));
        if (is_t) { out[c] = hi; out[49 + c] = hi; out[98 + c] = lo; }
        else      { out[c] = hi; out[49 + c] = lo; out[98 + c] = hi; }
    }
    for (int k = 147; k < KST; k++) out[k] = __float2bfloat16(0.0f);
}

// ---------------- 4) tensor GEMM: mma.sync m16n8k16 bf16, 128x128 tile ----------------
// 8 warps: warp (wid&3) -> 32-row band, (wid>>2) -> 64-col band. K = 160 (10 chunks).
#define GEMM_SMEM (2 * 128 * KST * 2)   // 86016 B
__global__ void __launch_bounds__(256, 2) k_gemm() {
    extern __shared__ __nv_bfloat16 smbf[];
    __nv_bfloat16* Xs = smbf;                  // [128][KST]
    __nv_bfloat16* Ys = smbf + 128 * KST;      // [128][KST]
    int t = threadIdx.x, wid = t >> 5, lid = t & 31;
    int bx = blockIdx.x, by = blockIdx.y;      // 50 x 50

    {   // tile loads: 128 rows x 21 uint4 each
        const uint4* xs = (const uint4*)&g_xr[(size_t)(by * 128) * KST];
        const uint4* ys = (const uint4*)&g_yr[(size_t)(bx * 128) * KST];
        uint4* X4 = (uint4*)Xs; uint4* Y4 = (uint4*)Ys;
        for (int i = t; i < 128 * 21; i += 256) { X4[i] = xs[i]; Y4[i] = ys[i]; }
    }
    __syncthreads();

    int MR = (wid & 3) * 32, NC = (wid >> 2) * 64;
    uint32_t xbase = smem_to_u32(Xs), ybase = smem_to_u32(Ys);
    // ldmatrix lane address pieces
    int arow = (lid & 7) + ((lid >> 3) & 1) * 8;   // A: tiles (m0-7 k0),(m8-15 k0),(m0-7 k8),(m8-15 k8)
    int akof = (lid >> 4) * 8;
    int brow = (lid & 7) + ((lid >> 4) & 1) * 8;   // B: tiles (n0-7 k0),(n0-7 k8),(n8-15 k0),(n8-15 k8)
    int bkof = ((lid >> 3) & 1) * 8;

    float acc[2][8][4];
#pragma unroll
    for (int i = 0; i < 2; i++)
#pragma unroll
        for (int j = 0; j < 8; j++)
#pragma unroll
            for (int e = 0; e < 4; e++) acc[i][j][e] = 0.0f;

#pragma unroll
    for (int k = 0; k < 10; k++) {
        int kb = k * 16;
        uint32_t a[2][4];
#pragma unroll
        for (int mt = 0; mt < 2; mt++)
            ldsm_x4(a[mt][0], a[mt][1], a[mt][2], a[mt][3],
                    xbase + ((MR + mt * 16 + arow) * KST + kb + akof) * 2);
        uint32_t b[8][2];
#pragma unroll
        for (int nt2 = 0; nt2 < 4; nt2++)
            ldsm_x4(b[2 * nt2][0], b[2 * nt2][1], b[2 * nt2 + 1][0], b[2 * nt2 + 1][1],
                    ybase + ((NC + nt2 * 16 + brow) * KST + kb + bkof) * 2);
#pragma unroll
        for (int mt = 0; mt < 2; mt++)
#pragma unroll
            for (int nt = 0; nt < 8; nt++)
                mma16816(acc[mt][nt], a[mt], b[nt]);
    }

    // epilogue: d = max((1-sim)/2,0) -> fp16 store + per-row packed-key argmin
    int g = lid >> 2, tq = lid & 3;
#pragma unroll
    for (int mt = 0; mt < 2; mt++) {
        int r0 = by * 128 + MR + mt * 16 + g;
        int r1 = r0 + 8;
        unsigned long long key0 = ~0ull, key1 = ~0ull;
#pragma unroll
        for (int nt = 0; nt < 8; nt++) {
            int col = bx * 128 + NC + nt * 8 + tq * 2;
            float d00 = fmaxf(__fmul_rn(__fadd_rn(1.0f, -acc[mt][nt][0]), 0.5f), 0.0f);
            float d01 = fmaxf(__fmul_rn(__fadd_rn(1.0f, -acc[mt][nt][1]), 0.5f), 0.0f);
            float d10 = fmaxf(__fmul_rn(__fadd_rn(1.0f, -acc[mt][nt][2]), 0.5f), 0.0f);
            float d11 = fmaxf(__fmul_rn(__fadd_rn(1.0f, -acc[mt][nt][3]), 0.5f), 0.0f);
            unsigned p0 = (unsigned)__half_as_ushort(__float2half_rn(d00)) |
                          ((unsigned)__half_as_ushort(__float2half_rn(d01)) << 16);
            unsigned p1 = (unsigned)__half_as_ushort(__float2half_rn(d10)) |
                          ((unsigned)__half_as_ushort(__float2half_rn(d11)) << 16);
            *(unsigned*)&g_dh[(size_t)r0 * NS + col] = p0;
            *(unsigned*)&g_dh[(size_t)r1 * NS + col] = p1;
            unsigned long long k00 = ((unsigned long long)__float_as_uint(d00) << 32) | (unsigned)col;
            unsigned long long k01 = ((unsigned long long)__float_as_uint(d01) << 32) | (unsigned)(col + 1);
            unsigned long long k10 = ((unsigned long long)__float_as_uint(d10) << 32) | (unsigned)col;
            unsigned long long k11 = ((unsigned long long)__float_as_uint(d11) << 32) | (unsigned)(col + 1);
            key0 = (k00 < key0) ? k00 : key0; key0 = (k01 < key0) ? k01 : key0;
            key1 = (k10 < key1) ? k10 : key1; key1 = (k11 < key1) ? k11 : key1;
        }
#pragma unroll
        for (int o = 1; o < 4; o <<= 1) {
            unsigned long long q0 = __shfl_xor_sync(0xffffffffu, key0, o);
            unsigned long long q1 = __shfl_xor_sync(0xffffffffu, key1, o);
            key0 = (q0 < key0) ? q0 : key0;
            key1 = (q1 < key1) ? q1 : key1;
        }
        if (tq == 0) {
            atomicMin(&g_amin[r0], key0);
            atomicMin(&g_amin[r1], key1);
        }
    }
}

// ---------------- 5) occurrence counts ----------------
__global__ void k_cnt() {
    int p = blockIdx.x * 256 + threadIdx.x;
    if (p < NS) {
        unsigned q = (unsigned)(g_amin[p] & 0xffffffffu);
        atomicAdd(&g_cnt[q], 1);
    }
}

// ---------------- 6) per-row min + sum-exp -> row loss (8 rows per block) ----------------
__global__ void __launch_bounds__(256) k_row() {
    extern __shared__ float dyn[];
    float* occ = dyn;               // [NS]
    float* sd  = dyn + NS;          // [NS]
    float* sr  = dyn + 2 * NS;      // [8]
    int t = threadIdx.x;

    for (int j = t; j < NS; j += 256) occ[j] = LAMB * (float)g_cnt[j];
    __syncthreads();

#pragma unroll 1
    for (int r = 0; r < 8; r++) {
        int p = blockIdx.x * 8 + r;
        const uint4* drow = (const uint4*)&g_dh[(size_t)p * NS];

        float m = 3.4e38f;
        for (int j8 = t; j8 < NS / 8; j8 += 256) {
            uint4 u = drow[j8];
            const __half* h = (const __half*)&u;
            int j = j8 * 8;
            float lm = 3.4e38f;
#pragma unroll
            for (int e = 0; e < 8; e++) {
                float v = __half2float(h[e]) + occ[j + e];
                sd[j + e] = v;
                lm = fminf(lm, v);
            }
            m = fminf(m, lm);
        }
#pragma unroll
        for (int o = 16; o; o >>= 1) m = fminf(m, __shfl_xor_sync(0xffffffffu, m, o));
        if ((t & 31) == 0) sr[t >> 5] = m;
        __syncthreads();
        if (t == 0) {
            float x = sr[0];
#pragma unroll
            for (int w = 1; w < 8; w++) x = fminf(x, sr[w]);
            sr[0] = x;
        }
        __syncthreads();
        m = sr[0];
        __syncthreads();

        float meps = __fadd_rn(m, EPSF);
        float inv = 1.0f / meps;

        float s = 0.0f;
        for (int j = t; j < NS; j += 256) {
            float rr = sd[j] * inv;
            s += __expf(__fmul_rn(__fadd_rn(1.0f, -rr), 2.0f));
        }
#pragma unroll
        for (int o = 16; o; o >>= 1) s += __shfl_xor_sync(0xffffffffu, s, o);
        if ((t & 31) == 0) sr[t >> 5] = s;
        __syncthreads();
        if (t == 0) {
            float st = 0.0f;
#pragma unroll
            for (int w = 0; w < 8; w++) st += sr[w];
            float emax = __fmul_rn(__fadd_rn(1.0f, -__fmul_rn(m, inv)), 2.0f);
            g_rowloss[p] = logf(st) - emax;
        }
        __syncthreads();
    }
}

// ---------------- 7) final mean ----------------
__global__ void k_final(float* __restrict__ out) {
    int t = threadIdx.x;
    float s = 0.0f;
    for (int p = t; p < NS; p += 256) s += g_rowloss[p];
    __shared__ float sm[256];
    sm[t] = s; __syncthreads();
    for (int st = 128; st; st >>= 1) { if (t < st) sm[t] += sm[t + st]; __syncthreads(); }
    if (t == 0) out[0] = sm[0] * (1.0f / (float)NS);
}

// ---------------- host launch ----------------
extern "C" void kernel_launch(void* const* d_in, const int* in_sizes, int n_in,
                              void* d_out, int out_size) {
    (void)in_sizes; (void)n_in; (void)out_size;
    const float* timg   = (const float*)d_in[0];
    const float* rimg   = (const float*)d_in[1];
    const float* tfield = (const float*)d_in[2];
    const float* rfield = (const float*)d_in[3];
    float* out = (float*)d_out;

    const int ROW_SMEM = (2 * NS + 8) * (int)sizeof(float);          // 51232 B
    cudaFuncSetAttribute(k_gemm, cudaFuncAttributeMaxDynamicSharedMemorySize, GEMM_SMEM);
    cudaFuncSetAttribute(k_row,  cudaFuncAttributeMaxDynamicSharedMemorySize, ROW_SMEM);

    k_idx  <<<50, 256>>>(tfield, rfield);
    k_mean <<<CCH, 256>>>(rimg);
    k_feat <<<dim3(25, 2), 256>>>(timg, rimg);
    k_gemm <<<dim3(50, 50), 256, GEMM_SMEM>>>();
    k_cnt  <<<25, 256>>>();
    k_row  <<<800, 256, ROW_SMEM>>>();
    k_final<<<1, 256>>>(out);
}

// round 9
// speedup vs baseline: 1.2303x; 1.2303x over previous
#include <cuda_runtime.h>
#include <cuda_fp16.h>
#include <cuda_bf16.h>
#include <cstdint>
#include <math.h>

// ---------------- problem constants ----------------
#define NS    6400          // SAMPLE*SAMPLE patches per image
#define CCH   49            // PATCH*PATCH channels
#define IMGW  512
#define GW    169           // (512-7)/3 + 1 patch-grid size
#define EPSF  2.2204460492503131e-16f
#define LAMB  0.05f
#define KST   168           // row stride in bf16 (160 active K + 8 pad)
#define DPAD  136           // d staging row stride in halves (128 + 8 pad)

// ---------------- device scratch ----------------
__device__ int   g_base_t[NS];
__device__ int   g_base_r[NS];
__device__ float g_ymean[CCH];
__device__ __nv_bfloat16 g_xr[(size_t)NS * KST];  // target rows [hi49|hi49|lo49|0...]
__device__ __nv_bfloat16 g_yr[(size_t)NS * KST];  // refer  rows [hi49|lo49|hi49|0...]
__device__ __half g_dh[(size_t)NS * NS];          // 81.92 MB distance matrix (fp16)
__device__ unsigned long long g_amin[NS];
__device__ int   g_cnt[NS];
__device__ float g_rowloss[NS];

// ---------------- warp-mma helpers ----------------
__device__ __forceinline__ uint32_t smem_to_u32(const void* p) {
    uint32_t a;
    asm("{ .reg .u64 t; cvta.to.shared.u64 t, %1; cvt.u32.u64 %0, t; }" : "=r"(a) : "l"(p));
    return a;
}
__device__ __forceinline__ void ldsm_x4(uint32_t& r0, uint32_t& r1, uint32_t& r2, uint32_t& r3,
                                        uint32_t addr) {
    asm volatile("ldmatrix.sync.aligned.m8n8.x4.shared.b16 {%0,%1,%2,%3}, [%4];"
                 : "=r"(r0), "=r"(r1), "=r"(r2), "=r"(r3) : "r"(addr));
}
__device__ __forceinline__ void mma16816(float* c, const uint32_t* a, const uint32_t* b) {
    asm volatile("mma.sync.aligned.m16n8k16.row.col.f32.bf16.bf16.f32 "
                 "{%0,%1,%2,%3}, {%4,%5,%6,%7}, {%8,%9}, {%0,%1,%2,%3};"
                 : "+f"(c[0]), "+f"(c[1]), "+f"(c[2]), "+f"(c[3])
                 : "r"(a[0]), "r"(a[1]), "r"(a[2]), "r"(a[3]), "r"(b[0]), "r"(b[1]));
}

// ---------------- 1) grid-sample nearest indices (+ init amin/cnt) ----------------
__global__ void k_idx(const float* __restrict__ tfield, const float* __restrict__ rfield) {
    int i = blockIdx.x * blockDim.x + threadIdx.x;
    if (i < NS) { g_amin[i] = ~0ull; g_cnt[i] = 0; }
    if (i >= 2 * NS) return;
    const float* f = (i < NS) ? tfield : rfield;
    int p = (i < NS) ? i : (i - NS);
    float gx = __fadd_rn(__fmul_rn(f[2 * p + 0], 2.0f), -1.0f);
    float gy = __fadd_rn(__fmul_rn(f[2 * p + 1], 2.0f), -1.0f);
    float fx = __fmul_rn(__fadd_rn(__fmul_rn(__fadd_rn(gx, 1.0f), (float)GW), -1.0f), 0.5f);
    float fy = __fmul_rn(__fadd_rn(__fmul_rn(__fadd_rn(gy, 1.0f), (float)GW), -1.0f), 0.5f);
    int ix = (int)rintf(fx); ix = ix < 0 ? 0 : (ix > GW - 1 ? GW - 1 : ix);
    int iy = (int)rintf(fy); iy = iy < 0 ? 0 : (iy > GW - 1 ? GW - 1 : iy);
    int base = (iy * 3) * IMGW + ix * 3;
    if (i < NS) g_base_t[p] = base; else g_base_r[p] = base;
}

// ---------------- 2) refer patch channel mean ----------------
__global__ void k_mean(const float* __restrict__ rimg) {
    int c = blockIdx.x;
    int off = (c / 7) * IMGW + (c % 7);
    int t = threadIdx.x;
    float s = 0.0f;
    for (int p = t; p < NS; p += 256) s += rimg[g_base_r[p] + off];
    __shared__ float sm[256];
    sm[t] = s; __syncthreads();
    for (int st = 128; st; st >>= 1) { if (t < st) sm[t] += sm[t + st]; __syncthreads(); }
    if (t == 0) g_ymean[c] = sm[0] * (1.0f / (float)NS);
}

// ---------------- 3) features -> bf16 hi/lo split rows (smem-staged coalesced writes) ----------------
// X row: [hi(49) | hi(49) | lo(49) | 0] ; Y row: [hi(49) | lo(49) | hi(49) | 0]
// X.Y = hi.hi + hi.lo + lo.hi  (drops only lo.lo ~2^-18)
__global__ void __launch_bounds__(128) k_feat(const float* __restrict__ timg,
                                              const float* __restrict__ rimg) {
    __shared__ __nv_bfloat16 srow[128 * KST];   // 43008 B
    int t = threadIdx.x;
    int p = blockIdx.x * 128 + t;               // gridDim.x = 50
    bool is_t = (blockIdx.y == 0);
    const float* img = is_t ? timg : rimg;
    int base = is_t ? g_base_t[p] : g_base_r[p];

    float v[CCH];
    float sq = 0.0f;
#pragma unroll
    for (int c = 0; c < CCH; c++) {
        v[c] = img[base + (c / 7) * IMGW + (c % 7)] - g_ymean[c];
        sq += v[c] * v[c];
    }
    float inv = 1.0f / (sqrtf(sq) + EPSF);
    __nv_bfloat16* row = &srow[t * KST];
#pragma unroll
    for (int c = 0; c < CCH; c++) {
        float val = v[c] * inv;
        __nv_bfloat16 hi = __float2bfloat16(val);
        __nv_bfloat16 lo = __float2bfloat16(val - __bfloat162float(hi));
        if (is_t) { row[c] = hi; row[49 + c] = hi; row[98 + c] = lo; }
        else      { row[c] = hi; row[49 + c] = lo; row[98 + c] = hi; }
    }
    for (int k = 147; k < KST; k++) row[k] = __float2bfloat16(0.0f);
    __syncthreads();

    // coalesced block copy: 128 rows x 21 uint4 contiguous
    uint4* dst = (uint4*)((is_t ? g_xr : g_yr) + (size_t)(blockIdx.x * 128) * KST);
    const uint4* src = (const uint4*)srow;
    for (int i = t; i < 128 * 21; i += 128) dst[i] = src[i];
}

// ---------------- 4) tensor GEMM: mma.sync m16n8k16 bf16, 128x128 tile ----------------
// 8 warps: warp (wid&3) -> 32-row band, (wid>>2) -> 64-col band. K = 160 (10 chunks).
#define GEMM_SMEM (2 * 128 * KST * 2)   // 86016 B
__global__ void __launch_bounds__(256, 2) k_gemm() {
    extern __shared__ __nv_bfloat16 smbf[];
    __nv_bfloat16* Xs = smbf;                  // [128][KST]
    __nv_bfloat16* Ys = smbf + 128 * KST;      // [128][KST]
    __half* Ds = (__half*)smbf;                // reused after mainloop: [128][DPAD]
    int t = threadIdx.x, wid = t >> 5, lid = t & 31;
    int bx = blockIdx.x, by = blockIdx.y;      // 50 x 50

    {   // tile loads: 128 rows x 21 uint4 each, contiguous
        const uint4* xs = (const uint4*)&g_xr[(size_t)(by * 128) * KST];
        const uint4* ys = (const uint4*)&g_yr[(size_t)(bx * 128) * KST];
        uint4* X4 = (uint4*)Xs; uint4* Y4 = (uint4*)Ys;
        for (int i = t; i < 128 * 21; i += 256) { X4[i] = xs[i]; Y4[i] = ys[i]; }
    }
    __syncthreads();

    int MR = (wid & 3) * 32, NC = (wid >> 2) * 64;
    uint32_t xbase = smem_to_u32(Xs), ybase = smem_to_u32(Ys);
    int arow = (lid & 7) + ((lid >> 3) & 1) * 8;
    int akof = (lid >> 4) * 8;
    int brow = (lid & 7) + ((lid >> 4) & 1) * 8;
    int bkof = ((lid >> 3) & 1) * 8;

    float acc[2][8][4];
#pragma unroll
    for (int i = 0; i < 2; i++)
#pragma unroll
        for (int j = 0; j < 8; j++)
#pragma unroll
            for (int e = 0; e < 4; e++) acc[i][j][e] = 0.0f;

#pragma unroll
    for (int k = 0; k < 10; k++) {
        int kb = k * 16;
        uint32_t a[2][4];
#pragma unroll
        for (int mt = 0; mt < 2; mt++)
            ldsm_x4(a[mt][0], a[mt][1], a[mt][2], a[mt][3],
                    xbase + ((MR + mt * 16 + arow) * KST + kb + akof) * 2);
        uint32_t b[8][2];
#pragma unroll
        for (int nt2 = 0; nt2 < 4; nt2++)
            ldsm_x4(b[2 * nt2][0], b[2 * nt2][1], b[2 * nt2 + 1][0], b[2 * nt2 + 1][1],
                    ybase + ((NC + nt2 * 16 + brow) * KST + kb + bkof) * 2);
#pragma unroll
        for (int mt = 0; mt < 2; mt++)
#pragma unroll
            for (int nt = 0; nt < 8; nt++)
                mma16816(acc[mt][nt], a[mt], b[nt]);
    }
    __syncthreads();   // everyone done reading Xs/Ys; Ds overwrites it

    // epilogue: d = max((1-sim)/2,0); argmin in regs + smem-staged coalesced store
    int g = lid >> 2, tq = lid & 3;
#pragma unroll
    for (int mt = 0; mt < 2; mt++) {
        int rl0 = MR + mt * 16 + g;
        int rl1 = rl0 + 8;
        int r0 = by * 128 + rl0, r1 = by * 128 + rl1;
        unsigned long long key0 = ~0ull, key1 = ~0ull;
#pragma unroll
        for (int nt = 0; nt < 8; nt++) {
            int cl = NC + nt * 8 + tq * 2;
            int col = bx * 128 + cl;
            float d00 = fmaxf(__fmul_rn(__fadd_rn(1.0f, -acc[mt][nt][0]), 0.5f), 0.0f);
            float d01 = fmaxf(__fmul_rn(__fadd_rn(1.0f, -acc[mt][nt][1]), 0.5f), 0.0f);
            float d10 = fmaxf(__fmul_rn(__fadd_rn(1.0f, -acc[mt][nt][2]), 0.5f), 0.0f);
            float d11 = fmaxf(__fmul_rn(__fadd_rn(1.0f, -acc[mt][nt][3]), 0.5f), 0.0f);
            unsigned p0 = (unsigned)__half_as_ushort(__float2half_rn(d00)) |
                          ((unsigned)__half_as_ushort(__float2half_rn(d01)) << 16);
            unsigned p1 = (unsigned)__half_as_ushort(__float2half_rn(d10)) |
                          ((unsigned)__half_as_ushort(__float2half_rn(d11)) << 16);
            *(unsigned*)&Ds[rl0 * DPAD + cl] = p0;
            *(unsigned*)&Ds[rl1 * DPAD + cl] = p1;
            unsigned long long k00 = ((unsigned long long)__float_as_uint(d00) << 32) | (unsigned)col;
            unsigned long long k01 = ((unsigned long long)__float_as_uint(d01) << 32) | (unsigned)(col + 1);
            unsigned long long k10 = ((unsigned long long)__float_as_uint(d10) << 32) | (unsigned)col;
            unsigned long long k11 = ((unsigned long long)__float_as_uint(d11) << 32) | (unsigned)(col + 1);
            key0 = (k00 < key0) ? k00 : key0; key0 = (k01 < key0) ? k01 : key0;
            key1 = (k10 < key1) ? k10 : key1; key1 = (k11 < key1) ? k11 : key1;
        }
#pragma unroll
        for (int o = 1; o < 4; o <<= 1) {
            unsigned long long q0 = __shfl_xor_sync(0xffffffffu, key0, o);
            unsigned long long q1 = __shfl_xor_sync(0xffffffffu, key1, o);
            key0 = (q0 < key0) ? q0 : key0;
            key1 = (q1 < key1) ? q1 : key1;
        }
        if (tq == 0) {
            atomicMin(&g_amin[r0], key0);
            atomicMin(&g_amin[r1], key1);
        }
    }
    __syncthreads();

    // coalesced store: 128 rows x 16 uint4 (256 B per row)
    {
        for (int i = t; i < 128 * 16; i += 256) {
            int row = i >> 4, c16 = i & 15;
            *(uint4*)&g_dh[(size_t)(by * 128 + row) * NS + bx * 128 + c16 * 8] =
                *(const uint4*)&Ds[row * DPAD + c16 * 8];
        }
    }
}

// ---------------- 5) occurrence counts ----------------
__global__ void k_cnt() {
    int p = blockIdx.x * 256 + threadIdx.x;
    if (p < NS) {
        unsigned q = (unsigned)(g_amin[p] & 0xffffffffu);
        atomicAdd(&g_cnt[q], 1);
    }
}

// ---------------- 6) per-row min + sum-exp -> row loss (8 rows per block) ----------------
__global__ void __launch_bounds__(256) k_row() {
    extern __shared__ float dyn[];
    float* occ = dyn;               // [NS]
    float* sd  = dyn + NS;          // [NS]
    float* sr  = dyn + 2 * NS;      // [8]
    int t = threadIdx.x;

    for (int j = t; j < NS; j += 256) occ[j] = LAMB * (float)g_cnt[j];
    __syncthreads();

#pragma unroll 1
    for (int r = 0; r < 8; r++) {
        int p = blockIdx.x * 8 + r;
        const uint4* drow = (const uint4*)&g_dh[(size_t)p * NS];

        float m = 3.4e38f;
        for (int j8 = t; j8 < NS / 8; j8 += 256) {
            uint4 u = drow[j8];
            const __half* h = (const __half*)&u;
            int j = j8 * 8;
            float lm = 3.4e38f;
#pragma unroll
            for (int e = 0; e < 8; e++) {
                float v = __half2float(h[e]) + occ[j + e];
                sd[j + e] = v;
                lm = fminf(lm, v);
            }
            m = fminf(m, lm);
        }
#pragma unroll
        for (int o = 16; o; o >>= 1) m = fminf(m, __shfl_xor_sync(0xffffffffu, m, o));
        if ((t & 31) == 0) sr[t >> 5] = m;
        __syncthreads();
        if (t == 0) {
            float x = sr[0];
#pragma unroll
            for (int w = 1; w < 8; w++) x = fminf(x, sr[w]);
            sr[0] = x;
        }
        __syncthreads();
        m = sr[0];
        __syncthreads();

        float meps = __fadd_rn(m, EPSF);
        float inv = 1.0f / meps;

        float s = 0.0f;
        for (int j = t; j < NS; j += 256) {
            float rr = sd[j] * inv;
            s += __expf(__fmul_rn(__fadd_rn(1.0f, -rr), 2.0f));
        }
#pragma unroll
        for (int o = 16; o; o >>= 1) s += __shfl_xor_sync(0xffffffffu, s, o);
        if ((t & 31) == 0) sr[t >> 5] = s;
        __syncthreads();
        if (t == 0) {
            float st = 0.0f;
#pragma unroll
            for (int w = 0; w < 8; w++) st += sr[w];
            float emax = __fmul_rn(__fadd_rn(1.0f, -__fmul_rn(m, inv)), 2.0f);
            g_rowloss[p] = logf(st) - emax;
        }
        __syncthreads();
    }
}

// ---------------- 7) final mean ----------------
__global__ void k_final(float* __restrict__ out) {
    int t = threadIdx.x;
    float s = 0.0f;
    for (int p = t; p < NS; p += 256) s += g_rowloss[p];
    __shared__ float sm[256];
    sm[t] = s; __syncthreads();
    for (int st = 128; st; st >>= 1) { if (t < st) sm[t] += sm[t + st]; __syncthreads(); }
    if (t == 0) out[0] = sm[0] * (1.0f / (float)NS);
}

// ---------------- host launch ----------------
extern "C" void kernel_launch(void* const* d_in, const int* in_sizes, int n_in,
                              void* d_out, int out_size) {
    (void)in_sizes; (void)n_in; (void)out_size;
    const float* timg   = (const float*)d_in[0];
    const float* rimg   = (const float*)d_in[1];
    const float* tfield = (const float*)d_in[2];
    const float* rfield = (const float*)d_in[3];
    float* out = (float*)d_out;

    const int ROW_SMEM = (2 * NS + 8) * (int)sizeof(float);          // 51232 B
    cudaFuncSetAttribute(k_gemm, cudaFuncAttributeMaxDynamicSharedMemorySize, GEMM_SMEM);
    cudaFuncSetAttribute(k_row,  cudaFuncAttributeMaxDynamicSharedMemorySize, ROW_SMEM);

    k_idx  <<<50, 256>>>(tfield, rfield);
    k_mean <<<CCH, 256>>>(rimg);
    k_feat <<<dim3(50, 2), 128>>>(timg, rimg);
    k_gemm <<<dim3(50, 50), 256, GEMM_SMEM>>>();
    k_cnt  <<<25, 256>>>();
    k_row  <<<800, 256, ROW_SMEM>>>();
    k_final<<<1, 256>>>(out);
}

// round 10
// speedup vs baseline: 1.2466x; 1.0132x over previous
#include <cuda_runtime.h>
#include <cuda_fp16.h>
#include <cuda_bf16.h>
#include <cstdint>
#include <math.h>

// ---------------- problem constants ----------------
#define NS    6400          // SAMPLE*SAMPLE patches per image
#define CCH   49            // PATCH*PATCH channels
#define IMGW  512
#define GW    169           // (512-7)/3 + 1 patch-grid size
#define EPSF  2.2204460492503131e-16f
#define LAMB  0.05f
#define KST   168           // row stride in bf16 (160 active K + 8 pad)
#define DPAD  136           // d staging row stride in halves (128 + 8 pad)

// ---------------- device scratch ----------------
__device__ int   g_base_t[NS];
__device__ int   g_base_r[NS];
__device__ float g_ymean[CCH];
__device__ __nv_bfloat16 g_xr[(size_t)NS * KST];  // target rows [hi49|hi49|lo49|0...]
__device__ __nv_bfloat16 g_yr[(size_t)NS * KST];  // refer  rows [hi49|lo49|hi49|0...]
__device__ __half g_dh[(size_t)NS * NS];          // 81.92 MB distance matrix (fp16)
__device__ unsigned long long g_amin[NS];
__device__ int   g_cnt[NS];
__device__ float g_rowloss[NS];

// ---------------- warp-mma helpers ----------------
__device__ __forceinline__ uint32_t smem_to_u32(const void* p) {
    uint32_t a;
    asm("{ .reg .u64 t; cvta.to.shared.u64 t, %1; cvt.u32.u64 %0, t; }" : "=r"(a) : "l"(p));
    return a;
}
__device__ __forceinline__ void ldsm_x4(uint32_t& r0, uint32_t& r1, uint32_t& r2, uint32_t& r3,
                                        uint32_t addr) {
    asm volatile("ldmatrix.sync.aligned.m8n8.x4.shared.b16 {%0,%1,%2,%3}, [%4];"
                 : "=r"(r0), "=r"(r1), "=r"(r2), "=r"(r3) : "r"(addr));
}
__device__ __forceinline__ void mma16816(float* c, const uint32_t* a, const uint32_t* b) {
    asm volatile("mma.sync.aligned.m16n8k16.row.col.f32.bf16.bf16.f32 "
                 "{%0,%1,%2,%3}, {%4,%5,%6,%7}, {%8,%9}, {%0,%1,%2,%3};"
                 : "+f"(c[0]), "+f"(c[1]), "+f"(c[2]), "+f"(c[3])
                 : "r"(a[0]), "r"(a[1]), "r"(a[2]), "r"(a[3]), "r"(b[0]), "r"(b[1]));
}

// ---------------- 1) grid-sample nearest indices (+ init amin/cnt) ----------------
__global__ void k_idx(const float* __restrict__ tfield, const float* __restrict__ rfield) {
    int i = blockIdx.x * blockDim.x + threadIdx.x;
    if (i < NS) { g_amin[i] = ~0ull; g_cnt[i] = 0; }
    if (i >= 2 * NS) return;
    const float* f = (i < NS) ? tfield : rfield;
    int p = (i < NS) ? i : (i - NS);
    float gx = __fadd_rn(__fmul_rn(f[2 * p + 0], 2.0f), -1.0f);
    float gy = __fadd_rn(__fmul_rn(f[2 * p + 1], 2.0f), -1.0f);
    float fx = __fmul_rn(__fadd_rn(__fmul_rn(__fadd_rn(gx, 1.0f), (float)GW), -1.0f), 0.5f);
    float fy = __fmul_rn(__fadd_rn(__fmul_rn(__fadd_rn(gy, 1.0f), (float)GW), -1.0f), 0.5f);
    int ix = (int)rintf(fx); ix = ix < 0 ? 0 : (ix > GW - 1 ? GW - 1 : ix);
    int iy = (int)rintf(fy); iy = iy < 0 ? 0 : (iy > GW - 1 ? GW - 1 : iy);
    int base = (iy * 3) * IMGW + ix * 3;
    if (i < NS) g_base_t[p] = base; else g_base_r[p] = base;
}

// ---------------- 2) refer patch channel mean ----------------
__global__ void k_mean(const float* __restrict__ rimg) {
    int c = blockIdx.x;
    int off = (c / 7) * IMGW + (c % 7);
    int t = threadIdx.x;
    float s = 0.0f;
    for (int p = t; p < NS; p += 256) s += rimg[g_base_r[p] + off];
    __shared__ float sm[256];
    sm[t] = s; __syncthreads();
    for (int st = 128; st; st >>= 1) { if (t < st) sm[t] += sm[t + st]; __syncthreads(); }
    if (t == 0) g_ymean[c] = sm[0] * (1.0f / (float)NS);
}

// ---------------- 3) features -> bf16 hi/lo split rows (smem-staged coalesced writes) ----------------
// X row: [hi(49) | hi(49) | lo(49) | 0] ; Y row: [hi(49) | lo(49) | hi(49) | 0]
// X.Y = hi.hi + hi.lo + lo.hi  (drops only lo.lo ~2^-18)
__global__ void __launch_bounds__(128) k_feat(const float* __restrict__ timg,
                                              const float* __restrict__ rimg) {
    __shared__ __nv_bfloat16 srow[128 * KST];   // 43008 B
    int t = threadIdx.x;
    int p = blockIdx.x * 128 + t;               // gridDim.x = 50
    bool is_t = (blockIdx.y == 0);
    const float* img = is_t ? timg : rimg;
    int base = is_t ? g_base_t[p] : g_base_r[p];

    float v[CCH];
    float sq = 0.0f;
#pragma unroll
    for (int c = 0; c < CCH; c++) {
        v[c] = img[base + (c / 7) * IMGW + (c % 7)] - g_ymean[c];
        sq += v[c] * v[c];
    }
    float inv = 1.0f / (sqrtf(sq) + EPSF);
    __nv_bfloat16* row = &srow[t * KST];
#pragma unroll
    for (int c = 0; c < CCH; c++) {
        float val = v[c] * inv;
        __nv_bfloat16 hi = __float2bfloat16(val);
        __nv_bfloat16 lo = __float2bfloat16(val - __bfloat162float(hi));
        if (is_t) { row[c] = hi; row[49 + c] = hi; row[98 + c] = lo; }
        else      { row[c] = hi; row[49 + c] = lo; row[98 + c] = hi; }
    }
    for (int k = 147; k < KST; k++) row[k] = __float2bfloat16(0.0f);
    __syncthreads();

    // coalesced block copy: 128 rows x 21 uint4 contiguous
    uint4* dst = (uint4*)((is_t ? g_xr : g_yr) + (size_t)(blockIdx.x * 128) * KST);
    const uint4* src = (const uint4*)srow;
    for (int i = t; i < 128 * 21; i += 128) dst[i] = src[i];
}

// ---------------- 4) tensor GEMM: mma.sync m16n8k16 bf16, 128x128 tile ----------------
// 8 warps: warp (wid&3) -> 32-row band, (wid>>2) -> 64-col band. K = 160 (10 chunks).
#define GEMM_SMEM (2 * 128 * KST * 2)   // 86016 B
__global__ void __launch_bounds__(256, 2) k_gemm() {
    extern __shared__ __nv_bfloat16 smbf[];
    __nv_bfloat16* Xs = smbf;                  // [128][KST]
    __nv_bfloat16* Ys = smbf + 128 * KST;      // [128][KST]
    __half* Ds = (__half*)smbf;                // reused after mainloop: [128][DPAD]
    int t = threadIdx.x, wid = t >> 5, lid = t & 31;
    int bx = blockIdx.x, by = blockIdx.y;      // 50 x 50

    {   // tile loads: 128 rows x 21 uint4 each, contiguous
        const uint4* xs = (const uint4*)&g_xr[(size_t)(by * 128) * KST];
        const uint4* ys = (const uint4*)&g_yr[(size_t)(bx * 128) * KST];
        uint4* X4 = (uint4*)Xs; uint4* Y4 = (uint4*)Ys;
        for (int i = t; i < 128 * 21; i += 256) { X4[i] = xs[i]; Y4[i] = ys[i]; }
    }
    __syncthreads();

    int MR = (wid & 3) * 32, NC = (wid >> 2) * 64;
    uint32_t xbase = smem_to_u32(Xs), ybase = smem_to_u32(Ys);
    int arow = (lid & 7) + ((lid >> 3) & 1) * 8;
    int akof = (lid >> 4) * 8;
    int brow = (lid & 7) + ((lid >> 4) & 1) * 8;
    int bkof = ((lid >> 3) & 1) * 8;

    float acc[2][8][4];
#pragma unroll
    for (int i = 0; i < 2; i++)
#pragma unroll
        for (int j = 0; j < 8; j++)
#pragma unroll
            for (int e = 0; e < 4; e++) acc[i][j][e] = 0.0f;

#pragma unroll
    for (int k = 0; k < 10; k++) {
        int kb = k * 16;
        uint32_t a[2][4];
#pragma unroll
        for (int mt = 0; mt < 2; mt++)
            ldsm_x4(a[mt][0], a[mt][1], a[mt][2], a[mt][3],
                    xbase + ((MR + mt * 16 + arow) * KST + kb + akof) * 2);
        uint32_t b[8][2];
#pragma unroll
        for (int nt2 = 0; nt2 < 4; nt2++)
            ldsm_x4(b[2 * nt2][0], b[2 * nt2][1], b[2 * nt2 + 1][0], b[2 * nt2 + 1][1],
                    ybase + ((NC + nt2 * 16 + brow) * KST + kb + bkof) * 2);
#pragma unroll
        for (int mt = 0; mt < 2; mt++)
#pragma unroll
            for (int nt = 0; nt < 8; nt++)
                mma16816(acc[mt][nt], a[mt], b[nt]);
    }
    __syncthreads();   // everyone done reading Xs/Ys; Ds overwrites it

    // epilogue: d = max(0.5 - 0.5*sim, 0); float-scan argmin + packed cvt + smem staging
    int g = lid >> 2, tq = lid & 3;
#pragma unroll
    for (int mt = 0; mt < 2; mt++) {
        int rl0 = MR + mt * 16 + g;
        int rl1 = rl0 + 8;
        float v0 = 1e30f, v1 = 1e30f;
        int i0 = 0, i1 = 0;
#pragma unroll
        for (int nt = 0; nt < 8; nt++) {
            int cl = NC + nt * 8 + tq * 2;
            int col = bx * 128 + cl;
            float d00 = fmaxf(fmaf(acc[mt][nt][0], -0.5f, 0.5f), 0.0f);
            float d01 = fmaxf(fmaf(acc[mt][nt][1], -0.5f, 0.5f), 0.0f);
            float d10 = fmaxf(fmaf(acc[mt][nt][2], -0.5f, 0.5f), 0.0f);
            float d11 = fmaxf(fmaf(acc[mt][nt][3], -0.5f, 0.5f), 0.0f);
            uint32_t p0, p1;
            asm("cvt.rn.f16x2.f32 %0, %1, %2;" : "=r"(p0) : "f"(d01), "f"(d00));
            asm("cvt.rn.f16x2.f32 %0, %1, %2;" : "=r"(p1) : "f"(d11), "f"(d10));
            *(uint32_t*)&Ds[rl0 * DPAD + cl] = p0;
            *(uint32_t*)&Ds[rl1 * DPAD + cl] = p1;
            if (d00 < v0) { v0 = d00; i0 = col; }
            if (d01 < v0) { v0 = d01; i0 = col + 1; }
            if (d10 < v1) { v1 = d10; i1 = col; }
            if (d11 < v1) { v1 = d11; i1 = col + 1; }
        }
#pragma unroll
        for (int o = 1; o < 4; o <<= 1) {
            float vo0 = __shfl_xor_sync(0xffffffffu, v0, o);
            int   io0 = __shfl_xor_sync(0xffffffffu, i0, o);
            if (vo0 < v0 || (vo0 == v0 && io0 < i0)) { v0 = vo0; i0 = io0; }
            float vo1 = __shfl_xor_sync(0xffffffffu, v1, o);
            int   io1 = __shfl_xor_sync(0xffffffffu, i1, o);
            if (vo1 < v1 || (vo1 == v1 && io1 < i1)) { v1 = vo1; i1 = io1; }
        }
        if (tq == 0) {
            atomicMin(&g_amin[by * 128 + rl0],
                      ((unsigned long long)__float_as_uint(v0) << 32) | (unsigned)i0);
            atomicMin(&g_amin[by * 128 + rl1],
                      ((unsigned long long)__float_as_uint(v1) << 32) | (unsigned)i1);
        }
    }
    __syncthreads();

    // coalesced store: 128 rows x 16 uint4 (256 B per row)
    {
        for (int i = t; i < 128 * 16; i += 256) {
            int row = i >> 4, c16 = i & 15;
            *(uint4*)&g_dh[(size_t)(by * 128 + row) * NS + bx * 128 + c16 * 8] =
                *(const uint4*)&Ds[row * DPAD + c16 * 8];
        }
    }
}

// ---------------- 5) occurrence counts ----------------
__global__ void k_cnt() {
    int p = blockIdx.x * 256 + threadIdx.x;
    if (p < NS) {
        unsigned q = (unsigned)(g_amin[p] & 0xffffffffu);
        atomicAdd(&g_cnt[q], 1);
    }
}

// ---------------- 6) per-row min + sum-exp -> row loss (8 rows per block) ----------------
__global__ void __launch_bounds__(256) k_row() {
    extern __shared__ float dyn[];
    float* occ = dyn;               // [NS]
    float* sd  = dyn + NS;          // [NS]
    float* sr  = dyn + 2 * NS;      // [8]
    int t = threadIdx.x;

    for (int j = t; j < NS; j += 256) occ[j] = LAMB * (float)g_cnt[j];
    __syncthreads();

#pragma unroll 1
    for (int r = 0; r < 8; r++) {
        int p = blockIdx.x * 8 + r;
        const uint4* drow = (const uint4*)&g_dh[(size_t)p * NS];

        float m = 3.4e38f;
        for (int j8 = t; j8 < NS / 8; j8 += 256) {
            uint4 u = drow[j8];
            const __half* h = (const __half*)&u;
            int j = j8 * 8;
            float lm = 3.4e38f;
#pragma unroll
            for (int e = 0; e < 8; e++) {
                float v = __half2float(h[e]) + occ[j + e];
                sd[j + e] = v;
                lm = fminf(lm, v);
            }
            m = fminf(m, lm);
        }
#pragma unroll
        for (int o = 16; o; o >>= 1) m = fminf(m, __shfl_xor_sync(0xffffffffu, m, o));
        if ((t & 31) == 0) sr[t >> 5] = m;
        __syncthreads();
        if (t == 0) {
            float x = sr[0];
#pragma unroll
            for (int w = 1; w < 8; w++) x = fminf(x, sr[w]);
            sr[0] = x;
        }
        __syncthreads();
        m = sr[0];
        __syncthreads();

        float meps = __fadd_rn(m, EPSF);
        float inv = 1.0f / meps;

        float s = 0.0f;
        for (int j = t; j < NS; j += 256) {
            float rr = sd[j] * inv;
            s += __expf(__fmul_rn(__fadd_rn(1.0f, -rr), 2.0f));
        }
#pragma unroll
        for (int o = 16; o; o >>= 1) s += __shfl_xor_sync(0xffffffffu, s, o);
        if ((t & 31) == 0) sr[t >> 5] = s;
        __syncthreads();
        if (t == 0) {
            float st = 0.0f;
#pragma unroll
            for (int w = 0; w < 8; w++) st += sr[w];
            float emax = __fmul_rn(__fadd_rn(1.0f, -__fmul_rn(m, inv)), 2.0f);
            g_rowloss[p] = logf(st) - emax;
        }
        __syncthreads();
    }
}

// ---------------- 7) final mean ----------------
__global__ void k_final(float* __restrict__ out) {
    int t = threadIdx.x;
    float s = 0.0f;
    for (int p = t; p < NS; p += 256) s += g_rowloss[p];
    __shared__ float sm[256];
    sm[t] = s; __syncthreads();
    for (int st = 128; st; st >>= 1) { if (t < st) sm[t] += sm[t + st]; __syncthreads(); }
    if (t == 0) out[0] = sm[0] * (1.0f / (float)NS);
}

// ---------------- host launch ----------------
extern "C" void kernel_launch(void* const* d_in, const int* in_sizes, int n_in,
                              void* d_out, int out_size) {
    (void)in_sizes; (void)n_in; (void)out_size;
    const float* timg   = (const float*)d_in[0];
    const float* rimg   = (const float*)d_in[1];
    const float* tfield = (const float*)d_in[2];
    const float* rfield = (const float*)d_in[3];
    float* out = (float*)d_out;

    const int ROW_SMEM = (2 * NS + 8) * (int)sizeof(float);          // 51232 B
    cudaFuncSetAttribute(k_gemm, cudaFuncAttributeMaxDynamicSharedMemorySize, GEMM_SMEM);
    cudaFuncSetAttribute(k_row,  cudaFuncAttributeMaxDynamicSharedMemorySize, ROW_SMEM);

    k_idx  <<<50, 256>>>(tfield, rfield);
    k_mean <<<CCH, 256>>>(rimg);
    k_feat <<<dim3(50, 2), 128>>>(timg, rimg);
    k_gemm <<<dim3(50, 50), 256, GEMM_SMEM>>>();
    k_cnt  <<<25, 256>>>();
    k_row  <<<800, 256, ROW_SMEM>>>();
    k_final<<<1, 256>>>(out);
}